// round 11
// baseline (speedup 1.0000x reference)
#include <cuda_runtime.h>
#include <cuda_bf16.h>
#include <math.h>

#define D_IN   128
#define D_OUT  128
#define KK     64
#define IC     16                 // i-rows per chunk
#define NCHUNK (D_IN / IC)        // 8 partial buffers
#define BC     128                // batch rows per block
#define BMAX   4096

// Scratch (__device__ globals per allocation-free rule)
__device__ float g_CD[D_IN * KK * 2 * D_OUT];        // [i][k][{ct,dt}][o]  8MB
__device__ float g_part[NCHUNK * BMAX * D_OUT];      // partial sums       16MB

// ---------------------------------------------------------------------------
// Prep: fused PCHIP slopes + transpose, ONE barrier.
// Block = (i, 32-wide o-tile). Reads coeffs[o][i][k] coalesced into padded
// smem, then each thread computes slopes for 8 k's (re-deriving the 2 deltas
// it needs from sy directly -> no delta array, no second barrier) and writes
// g_CD[i][k][{c,d}][o] with 128B-coalesced stores.
// ---------------------------------------------------------------------------
__global__ void __launch_bounds__(256) prep_kernel(const float* __restrict__ coeffs) {
    __shared__ float sy[32][KK + 1];   // +1 pad -> stride 65, conflict-free columns
    const int i  = blockIdx.x;
    const int o0 = blockIdx.y * 32;
    const int t  = threadIdx.x;
    const float hk   = 1.0f / 63.0f;
    const float EPSf = 1e-12f;

    // Coalesced load: 2048 floats, 8 per thread
    #pragma unroll
    for (int j = 0; j < 8; j++) {
        const int lin = t + j * 256;
        const int ol  = lin >> 6;
        const int k   = lin & 63;
        sy[ol][k] = coeffs[((size_t)(o0 + ol) * D_IN + i) * KK + k];
    }
    __syncthreads();

    const int ol = t & 31;      // lanes sweep o -> smem stride 65 (conflict-free)
    const int kb = t >> 5;      // warp owns 8 consecutive k
    const int o  = o0 + ol;

    #pragma unroll
    for (int kk = 0; kk < 8; kk++) {
        const int k = kb * 8 + kk;
        float dk;
        if (k == 0) {
            float d0 = (sy[ol][1] - sy[ol][0]) / (hk + EPSf);
            float d1 = (sy[ol][2] - sy[ol][1]) / (hk + EPSf);
            float di = (3.0f * hk * d0 - hk * d1) / (2.0f * hk + EPSf);
            if (di * d0 <= 0.0f) di = 0.0f;
            if (fabsf(di) > 3.0f * fabsf(d0)) di = 3.0f * d0;
            dk = di;
        } else if (k == 63) {
            float d62 = (sy[ol][63] - sy[ol][62]) / (hk + EPSf);
            float d61 = (sy[ol][62] - sy[ol][61]) / (hk + EPSf);
            float di  = (3.0f * hk * d62 - hk * d61) / (2.0f * hk + EPSf);
            if (di * d62 <= 0.0f) di = 0.0f;
            if (fabsf(di) > 3.0f * fabsf(d62)) di = 3.0f * d62;
            dk = di;
        } else {
            float dm = (sy[ol][k]     - sy[ol][k - 1]) / (hk + EPSf);
            float dp = (sy[ol][k + 1] - sy[ol][k])     / (hk + EPSf);
            dk = 0.0f;
            if (dm * dp > 0.0f) {
                const float w = 3.0f * hk;             // uniform knots: w1 = w2 = 3h
                float denom = w / (dm + EPSf) + w / (dp + EPSf);
                dk = (2.0f * w) / (denom + EPSf);
            }
        }
        const size_t off = ((size_t)i * KK + k) * 2 * D_OUT + o;
        g_CD[off]         = sy[ol][k];   // ct
        g_CD[off + D_OUT] = dk;          // dt
    }
}

// ---------------------------------------------------------------------------
// Main eval. Block = (BC=128 batch rows) x (IC=16 i's), 256 threads = 8 warps.
// Each warp covers all 128 o via float4 (lane*4) and owns 16 batch rows
// (acc = 16 x float4 registers).
// Per i: the 4 boundary rows (k=0 ct/dt, k=63 ct/dt) are cached in REGISTERS;
// extrapolated samples (~66%) need ZERO table reads. Interior samples gather
// 2KB contiguous (ct/dt at idx, idx+1) straight from L1/L2 via __ldg.
// Weights precomputed once per (b,i) into smem, broadcast-read per row.
// ---------------------------------------------------------------------------
__global__ void __launch_bounds__(256) kan_eval(const float* __restrict__ x, int B) {
    __shared__ float4 s_w[IC][BC];    // 32KB
    __shared__ int    s_idx[IC][BC];  //  8KB   code: 0..62 interior, 101 left, 102 right

    const int t    = threadIdx.x;
    const int lane = t & 31;
    const int wid  = t >> 5;
    const int b0   = blockIdx.x * BC;
    const int i0   = blockIdx.y * IC;
    const float hk = 1.0f / 63.0f;

    // Phase 1: per-(b,i) weights. 2048 pairs = 2 float4 x-reads per thread.
    #pragma unroll
    for (int j = 0; j < 2; j++) {
        const int q   = t + j * 256;
        const int bl  = q >> 2;
        const int icq = (q & 3) * 4;
        const float4 xv4 = *reinterpret_cast<const float4*>(
            x + (size_t)(b0 + bl) * D_IN + i0 + icq);
        const float xs[4] = {xv4.x, xv4.y, xv4.z, xv4.w};
        #pragma unroll
        for (int qq = 0; qq < 4; qq++) {
            const float xv = xs[qq];
            float4 w; int code;
            if (xv < 0.0f)      { code = 101; w = make_float4(0.f, xv,        0.f, 0.f); }
            else if (xv > 1.0f) { code = 102; w = make_float4(0.f, xv - 1.0f, 0.f, 0.f); }
            else {
                int idx = (int)floorf(xv / hk);
                idx = min(max(idx, 0), KK - 2);
                const float tt = (xv - (float)idx * hk) / hk;
                const float t2 = tt * tt, t3 = t2 * tt;
                w.x = 2.0f * t3 - 3.0f * t2 + 1.0f;    // h00
                w.y = hk * (t3 - 2.0f * t2 + tt);       // h*h10
                w.z = -2.0f * t3 + 3.0f * t2;           // h01
                w.w = hk * (t3 - t2);                   // h*h11
                code = idx;
            }
            s_w[icq + qq][bl]   = w;
            s_idx[icq + qq][bl] = code;
        }
    }
    __syncthreads();

    float4 acc[16];
    #pragma unroll
    for (int r = 0; r < 16; r++) acc[r] = make_float4(0.f, 0.f, 0.f, 0.f);

    for (int ic = 0; ic < IC; ic++) {
        const float4* bi4 = reinterpret_cast<const float4*>(
            g_CD + (size_t)(i0 + ic) * KK * 2 * D_OUT);
        // Register-cached boundary rows for this i (o-quad = lane*4)
        const float4 c0 = __ldg(bi4 + lane);
        const float4 d0 = __ldg(bi4 + 32 + lane);
        const float4 cL = __ldg(bi4 + 63 * 64 + lane);
        const float4 dL = __ldg(bi4 + 63 * 64 + 32 + lane);

        #pragma unroll 4
        for (int r = 0; r < 16; r++) {
            const int    bl   = wid * 16 + r;
            const int    code = s_idx[ic][bl];    // broadcast
            const float4 w    = s_w[ic][bl];      // broadcast
            if (code < 64) {                       // interior (warp-uniform branch)
                const float4* p = bi4 + code * 64 + lane;
                const float4 y0  = __ldg(p);
                const float4 dd0 = __ldg(p + 32);
                const float4 y1  = __ldg(p + 64);
                const float4 dd1 = __ldg(p + 96);
                acc[r].x += w.x * y0.x + w.y * dd0.x + w.z * y1.x + w.w * dd1.x;
                acc[r].y += w.x * y0.y + w.y * dd0.y + w.z * y1.y + w.w * dd1.y;
                acc[r].z += w.x * y0.z + w.y * dd0.z + w.z * y1.z + w.w * dd1.z;
                acc[r].w += w.x * y0.w + w.y * dd0.w + w.z * y1.w + w.w * dd1.w;
            } else {                               // extrapolation: registers only
                const float4 c = (code == 101) ? c0 : cL;
                const float4 d = (code == 101) ? d0 : dL;
                acc[r].x += c.x + w.y * d.x;
                acc[r].y += c.y + w.y * d.y;
                acc[r].z += c.z + w.y * d.z;
                acc[r].w += c.w + w.y * d.w;
            }
        }
    }

    // Write partials (float4, fully coalesced)
    #pragma unroll
    for (int r = 0; r < 16; r++) {
        const int b = b0 + wid * 16 + r;
        *reinterpret_cast<float4*>(
            g_part + ((size_t)blockIdx.y * B + b) * D_OUT + lane * 4) = acc[r];
    }
}

// ---------------------------------------------------------------------------
// Reduce 8 partial buffers + bias -> out. float4-vectorized.
// ---------------------------------------------------------------------------
__global__ void __launch_bounds__(256) reduce_kernel(const float* __restrict__ bias,
                                                     float* __restrict__ out, int B) {
    const int idx = blockIdx.x * 256 + threadIdx.x;   // float4 index
    const int n4  = B * (D_OUT / 4);
    if (idx >= n4) return;
    const float4* p = reinterpret_cast<const float4*>(g_part);
    const size_t stride = (size_t)B * (D_OUT / 4);
    float4 s = make_float4(0.f, 0.f, 0.f, 0.f);
    #pragma unroll
    for (int c = 0; c < NCHUNK; c++) {
        float4 v = __ldg(p + (size_t)c * stride + idx);
        s.x += v.x; s.y += v.y; s.z += v.z; s.w += v.w;
    }
    const float4 bv = __ldg(reinterpret_cast<const float4*>(bias) + (idx & (D_OUT / 4 - 1)));
    s.x += bv.x; s.y += bv.y; s.z += bv.z; s.w += bv.w;
    reinterpret_cast<float4*>(out)[idx] = s;
}

// ---------------------------------------------------------------------------
extern "C" void kernel_launch(void* const* d_in, const int* in_sizes, int n_in,
                              void* d_out, int out_size) {
    const float* x      = (const float*)d_in[0];   // [B, 128]
    const float* coeffs = (const float*)d_in[1];   // [128, 128, 64]
    const float* bias   = (const float*)d_in[2];   // [128]
    // d_in[3] = knots: uniform linspace(0,1,64) -> baked-in constants.

    const int B = in_sizes[0] / D_IN;              // 4096

    prep_kernel<<<dim3(D_IN, D_OUT / 32), 256>>>(coeffs);
    kan_eval<<<dim3(B / BC, NCHUNK), 256>>>(x, B);
    reduce_kernel<<<(B * (D_OUT / 4) + 255) / 256, 256>>>(bias, (float*)d_out, B);
}

// round 12
// speedup vs baseline: 1.0063x; 1.0063x over previous
#include <cuda_runtime.h>
#include <cuda_bf16.h>
#include <math.h>

#define D_IN   128
#define D_OUT  128
#define KK     64
#define IC     16                 // i-rows per chunk
#define NCHUNK (D_IN / IC)        // 8 partial buffers
#define BC     128                // batch rows per block
#define BMAX   4096

// Scratch (__device__ globals per allocation-free rule)
__device__ float g_CD[D_IN * KK * 2 * D_OUT];        // [i][k][{ct,dt}][o]  8MB
__device__ float g_part[NCHUNK * BMAX * D_OUT];      // partial sums       16MB

// ---------------------------------------------------------------------------
// Prep: fused PCHIP slopes + transpose, ONE barrier.
// Block = (i, 32-wide o-tile). Reads coeffs[o][i][k] coalesced into padded
// smem, then each thread computes slopes for 8 k's (re-deriving the 2 deltas
// it needs from sy directly -> no delta array, no second barrier) and writes
// g_CD[i][k][{c,d}][o] with 128B-coalesced stores.
// ---------------------------------------------------------------------------
__global__ void __launch_bounds__(256) prep_kernel(const float* __restrict__ coeffs) {
    __shared__ float sy[32][KK + 1];   // +1 pad -> stride 65, conflict-free columns
    const int i  = blockIdx.x;
    const int o0 = blockIdx.y * 32;
    const int t  = threadIdx.x;
    const float hk   = 1.0f / 63.0f;
    const float EPSf = 1e-12f;

    // Coalesced load: 2048 floats, 8 per thread
    #pragma unroll
    for (int j = 0; j < 8; j++) {
        const int lin = t + j * 256;
        const int ol  = lin >> 6;
        const int k   = lin & 63;
        sy[ol][k] = coeffs[((size_t)(o0 + ol) * D_IN + i) * KK + k];
    }
    __syncthreads();

    const int ol = t & 31;      // lanes sweep o -> smem stride 65 (conflict-free)
    const int kb = t >> 5;      // warp owns 8 consecutive k
    const int o  = o0 + ol;

    #pragma unroll
    for (int kk = 0; kk < 8; kk++) {
        const int k = kb * 8 + kk;
        float dk;
        if (k == 0) {
            float d0 = (sy[ol][1] - sy[ol][0]) / (hk + EPSf);
            float d1 = (sy[ol][2] - sy[ol][1]) / (hk + EPSf);
            float di = (3.0f * hk * d0 - hk * d1) / (2.0f * hk + EPSf);
            if (di * d0 <= 0.0f) di = 0.0f;
            if (fabsf(di) > 3.0f * fabsf(d0)) di = 3.0f * d0;
            dk = di;
        } else if (k == 63) {
            float d62 = (sy[ol][63] - sy[ol][62]) / (hk + EPSf);
            float d61 = (sy[ol][62] - sy[ol][61]) / (hk + EPSf);
            float di  = (3.0f * hk * d62 - hk * d61) / (2.0f * hk + EPSf);
            if (di * d62 <= 0.0f) di = 0.0f;
            if (fabsf(di) > 3.0f * fabsf(d62)) di = 3.0f * d62;
            dk = di;
        } else {
            float dm = (sy[ol][k]     - sy[ol][k - 1]) / (hk + EPSf);
            float dp = (sy[ol][k + 1] - sy[ol][k])     / (hk + EPSf);
            dk = 0.0f;
            if (dm * dp > 0.0f) {
                const float w = 3.0f * hk;             // uniform knots: w1 = w2 = 3h
                float denom = w / (dm + EPSf) + w / (dp + EPSf);
                dk = (2.0f * w) / (denom + EPSf);
            }
        }
        const size_t off = ((size_t)i * KK + k) * 2 * D_OUT + o;
        g_CD[off]         = sy[ol][k];   // ct
        g_CD[off + D_OUT] = dk;          // dt
    }
}

// ---------------------------------------------------------------------------
// Main eval. Block = (BC=128 batch rows) x (IC=16 i's), 256 threads = 8 warps.
// Each warp covers all 128 o via float4 (lane*4) and owns 16 batch rows
// (acc = 16 x float4 registers).
// Per i: the 4 boundary rows (k=0 ct/dt, k=63 ct/dt) are cached in REGISTERS;
// extrapolated samples (~66%) need ZERO table reads. Interior samples gather
// 2KB contiguous (ct/dt at idx, idx+1) straight from L1/L2 via __ldg.
// Weights precomputed once per (b,i) into smem, broadcast-read per row.
// ---------------------------------------------------------------------------
__global__ void __launch_bounds__(256) kan_eval(const float* __restrict__ x, int B) {
    __shared__ float4 s_w[IC][BC];    // 32KB
    __shared__ int    s_idx[IC][BC];  //  8KB   code: 0..62 interior, 101 left, 102 right

    const int t    = threadIdx.x;
    const int lane = t & 31;
    const int wid  = t >> 5;
    const int b0   = blockIdx.x * BC;
    const int i0   = blockIdx.y * IC;
    const float hk = 1.0f / 63.0f;

    // Phase 1: per-(b,i) weights. 2048 pairs = 2 float4 x-reads per thread.
    #pragma unroll
    for (int j = 0; j < 2; j++) {
        const int q   = t + j * 256;
        const int bl  = q >> 2;
        const int icq = (q & 3) * 4;
        const float4 xv4 = *reinterpret_cast<const float4*>(
            x + (size_t)(b0 + bl) * D_IN + i0 + icq);
        const float xs[4] = {xv4.x, xv4.y, xv4.z, xv4.w};
        #pragma unroll
        for (int qq = 0; qq < 4; qq++) {
            const float xv = xs[qq];
            float4 w; int code;
            if (xv < 0.0f)      { code = 101; w = make_float4(0.f, xv,        0.f, 0.f); }
            else if (xv > 1.0f) { code = 102; w = make_float4(0.f, xv - 1.0f, 0.f, 0.f); }
            else {
                int idx = (int)floorf(xv / hk);
                idx = min(max(idx, 0), KK - 2);
                const float tt = (xv - (float)idx * hk) / hk;
                const float t2 = tt * tt, t3 = t2 * tt;
                w.x = 2.0f * t3 - 3.0f * t2 + 1.0f;    // h00
                w.y = hk * (t3 - 2.0f * t2 + tt);       // h*h10
                w.z = -2.0f * t3 + 3.0f * t2;           // h01
                w.w = hk * (t3 - t2);                   // h*h11
                code = idx;
            }
            s_w[icq + qq][bl]   = w;
            s_idx[icq + qq][bl] = code;
        }
    }
    __syncthreads();

    float4 acc[16];
    #pragma unroll
    for (int r = 0; r < 16; r++) acc[r] = make_float4(0.f, 0.f, 0.f, 0.f);

    for (int ic = 0; ic < IC; ic++) {
        const float4* bi4 = reinterpret_cast<const float4*>(
            g_CD + (size_t)(i0 + ic) * KK * 2 * D_OUT);
        // Register-cached boundary rows for this i (o-quad = lane*4)
        const float4 c0 = __ldg(bi4 + lane);
        const float4 d0 = __ldg(bi4 + 32 + lane);
        const float4 cL = __ldg(bi4 + 63 * 64 + lane);
        const float4 dL = __ldg(bi4 + 63 * 64 + 32 + lane);

        #pragma unroll 4
        for (int r = 0; r < 16; r++) {
            const int    bl   = wid * 16 + r;
            const int    code = s_idx[ic][bl];    // broadcast
            const float4 w    = s_w[ic][bl];      // broadcast
            if (code < 64) {                       // interior (warp-uniform branch)
                const float4* p = bi4 + code * 64 + lane;
                const float4 y0  = __ldg(p);
                const float4 dd0 = __ldg(p + 32);
                const float4 y1  = __ldg(p + 64);
                const float4 dd1 = __ldg(p + 96);
                acc[r].x += w.x * y0.x + w.y * dd0.x + w.z * y1.x + w.w * dd1.x;
                acc[r].y += w.x * y0.y + w.y * dd0.y + w.z * y1.y + w.w * dd1.y;
                acc[r].z += w.x * y0.z + w.y * dd0.z + w.z * y1.z + w.w * dd1.z;
                acc[r].w += w.x * y0.w + w.y * dd0.w + w.z * y1.w + w.w * dd1.w;
            } else {                               // extrapolation: registers only
                const float4 c = (code == 101) ? c0 : cL;
                const float4 d = (code == 101) ? d0 : dL;
                acc[r].x += c.x + w.y * d.x;
                acc[r].y += c.y + w.y * d.y;
                acc[r].z += c.z + w.y * d.z;
                acc[r].w += c.w + w.y * d.w;
            }
        }
    }

    // Write partials (float4, fully coalesced)
    #pragma unroll
    for (int r = 0; r < 16; r++) {
        const int b = b0 + wid * 16 + r;
        *reinterpret_cast<float4*>(
            g_part + ((size_t)blockIdx.y * B + b) * D_OUT + lane * 4) = acc[r];
    }
}

// ---------------------------------------------------------------------------
// Reduce 8 partial buffers + bias -> out. float4-vectorized.
// ---------------------------------------------------------------------------
__global__ void __launch_bounds__(256) reduce_kernel(const float* __restrict__ bias,
                                                     float* __restrict__ out, int B) {
    const int idx = blockIdx.x * 256 + threadIdx.x;   // float4 index
    const int n4  = B * (D_OUT / 4);
    if (idx >= n4) return;
    const float4* p = reinterpret_cast<const float4*>(g_part);
    const size_t stride = (size_t)B * (D_OUT / 4);
    float4 s = make_float4(0.f, 0.f, 0.f, 0.f);
    #pragma unroll
    for (int c = 0; c < NCHUNK; c++) {
        float4 v = __ldg(p + (size_t)c * stride + idx);
        s.x += v.x; s.y += v.y; s.z += v.z; s.w += v.w;
    }
    const float4 bv = __ldg(reinterpret_cast<const float4*>(bias) + (idx & (D_OUT / 4 - 1)));
    s.x += bv.x; s.y += bv.y; s.z += bv.z; s.w += bv.w;
    reinterpret_cast<float4*>(out)[idx] = s;
}

// ---------------------------------------------------------------------------
extern "C" void kernel_launch(void* const* d_in, const int* in_sizes, int n_in,
                              void* d_out, int out_size) {
    const float* x      = (const float*)d_in[0];   // [B, 128]
    const float* coeffs = (const float*)d_in[1];   // [128, 128, 64]
    const float* bias   = (const float*)d_in[2];   // [128]
    // d_in[3] = knots: uniform linspace(0,1,64) -> baked-in constants.

    const int B = in_sizes[0] / D_IN;              // 4096

    prep_kernel<<<dim3(D_IN, D_OUT / 32), 256>>>(coeffs);
    kan_eval<<<dim3(B / BC, NCHUNK), 256>>>(x, B);
    reduce_kernel<<<(B * (D_OUT / 4) + 255) / 256, 256>>>(bias, (float*)d_out, B);
}

// round 13
// speedup vs baseline: 1.0318x; 1.0253x over previous
#include <cuda_runtime.h>
#include <cuda_bf16.h>
#include <math.h>

#define D_IN   128
#define D_OUT  128
#define KK     64
#define IC     16                 // i-rows per chunk
#define NCHUNK (D_IN / IC)        // 8 partial buffers
#define BC     128                // batch rows per block
#define BMAX   4096

// Scratch (__device__ globals per allocation-free rule)
__device__ float g_CD[D_IN * KK * 2 * D_OUT];        // [i][k][{ct,dt}][o]  8MB
__device__ float g_part[NCHUNK * BMAX * D_OUT];      // partial sums       16MB

// ---------------------------------------------------------------------------
// Prep: fused PCHIP slopes + transpose, ONE barrier.
// Block = (i, 32-wide o-tile). Reads coeffs[o][i][k] coalesced into padded
// smem, then each thread computes slopes for 8 k's (re-deriving the 2 deltas
// it needs from sy directly -> no delta array, no second barrier) and writes
// g_CD[i][k][{c,d}][o] with 128B-coalesced stores.
// ---------------------------------------------------------------------------
__global__ void __launch_bounds__(256) prep_kernel(const float* __restrict__ coeffs) {
    __shared__ float sy[32][KK + 1];   // +1 pad -> stride 65, conflict-free columns
    const int i  = blockIdx.x;
    const int o0 = blockIdx.y * 32;
    const int t  = threadIdx.x;
    const float hk   = 1.0f / 63.0f;
    const float EPSf = 1e-12f;

    // Coalesced load: 2048 floats, 8 per thread
    #pragma unroll
    for (int j = 0; j < 8; j++) {
        const int lin = t + j * 256;
        const int ol  = lin >> 6;
        const int k   = lin & 63;
        sy[ol][k] = coeffs[((size_t)(o0 + ol) * D_IN + i) * KK + k];
    }
    __syncthreads();

    const int ol = t & 31;      // lanes sweep o -> smem stride 65 (conflict-free)
    const int kb = t >> 5;      // warp owns 8 consecutive k
    const int o  = o0 + ol;

    #pragma unroll
    for (int kk = 0; kk < 8; kk++) {
        const int k = kb * 8 + kk;
        float dk;
        if (k == 0) {
            float d0 = (sy[ol][1] - sy[ol][0]) / (hk + EPSf);
            float d1 = (sy[ol][2] - sy[ol][1]) / (hk + EPSf);
            float di = (3.0f * hk * d0 - hk * d1) / (2.0f * hk + EPSf);
            if (di * d0 <= 0.0f) di = 0.0f;
            if (fabsf(di) > 3.0f * fabsf(d0)) di = 3.0f * d0;
            dk = di;
        } else if (k == 63) {
            float d62 = (sy[ol][63] - sy[ol][62]) / (hk + EPSf);
            float d61 = (sy[ol][62] - sy[ol][61]) / (hk + EPSf);
            float di  = (3.0f * hk * d62 - hk * d61) / (2.0f * hk + EPSf);
            if (di * d62 <= 0.0f) di = 0.0f;
            if (fabsf(di) > 3.0f * fabsf(d62)) di = 3.0f * d62;
            dk = di;
        } else {
            float dm = (sy[ol][k]     - sy[ol][k - 1]) / (hk + EPSf);
            float dp = (sy[ol][k + 1] - sy[ol][k])     / (hk + EPSf);
            dk = 0.0f;
            if (dm * dp > 0.0f) {
                const float w = 3.0f * hk;             // uniform knots: w1 = w2 = 3h
                float denom = w / (dm + EPSf) + w / (dp + EPSf);
                dk = (2.0f * w) / (denom + EPSf);
            }
        }
        const size_t off = ((size_t)i * KK + k) * 2 * D_OUT + o;
        g_CD[off]         = sy[ol][k];   // ct
        g_CD[off + D_OUT] = dk;          // dt
    }
}

// ---------------------------------------------------------------------------
// Main eval. Block = (BC=128 batch rows) x (IC=16 i's), 256 threads = 8 warps.
// Each warp covers all 128 o via float4 (lane*4) and owns 16 batch rows
// (acc = 16 x float4 registers).
// Per i: the 4 boundary rows (k=0 ct/dt, k=63 ct/dt) are cached in REGISTERS;
// extrapolated samples (~66%) need ZERO table reads. Interior samples gather
// 2KB contiguous (ct/dt at idx, idx+1) straight from L1/L2 via __ldg.
// Weights precomputed once per (b,i) into smem, broadcast-read per row.
// ---------------------------------------------------------------------------
__global__ void __launch_bounds__(256) kan_eval(const float* __restrict__ x, int B) {
    __shared__ float4 s_w[IC][BC];    // 32KB
    __shared__ int    s_idx[IC][BC];  //  8KB   code: 0..62 interior, 101 left, 102 right

    const int t    = threadIdx.x;
    const int lane = t & 31;
    const int wid  = t >> 5;
    const int b0   = blockIdx.x * BC;
    const int i0   = blockIdx.y * IC;
    const float hk = 1.0f / 63.0f;

    // Phase 1: per-(b,i) weights. 2048 pairs = 2 float4 x-reads per thread.
    #pragma unroll
    for (int j = 0; j < 2; j++) {
        const int q   = t + j * 256;
        const int bl  = q >> 2;
        const int icq = (q & 3) * 4;
        const float4 xv4 = *reinterpret_cast<const float4*>(
            x + (size_t)(b0 + bl) * D_IN + i0 + icq);
        const float xs[4] = {xv4.x, xv4.y, xv4.z, xv4.w};
        #pragma unroll
        for (int qq = 0; qq < 4; qq++) {
            const float xv = xs[qq];
            float4 w; int code;
            if (xv < 0.0f)      { code = 101; w = make_float4(0.f, xv,        0.f, 0.f); }
            else if (xv > 1.0f) { code = 102; w = make_float4(0.f, xv - 1.0f, 0.f, 0.f); }
            else {
                int idx = (int)floorf(xv / hk);
                idx = min(max(idx, 0), KK - 2);
                const float tt = (xv - (float)idx * hk) / hk;
                const float t2 = tt * tt, t3 = t2 * tt;
                w.x = 2.0f * t3 - 3.0f * t2 + 1.0f;    // h00
                w.y = hk * (t3 - 2.0f * t2 + tt);       // h*h10
                w.z = -2.0f * t3 + 3.0f * t2;           // h01
                w.w = hk * (t3 - t2);                   // h*h11
                code = idx;
            }
            s_w[icq + qq][bl]   = w;
            s_idx[icq + qq][bl] = code;
        }
    }
    __syncthreads();

    float4 acc[16];
    #pragma unroll
    for (int r = 0; r < 16; r++) acc[r] = make_float4(0.f, 0.f, 0.f, 0.f);

    for (int ic = 0; ic < IC; ic++) {
        const float4* bi4 = reinterpret_cast<const float4*>(
            g_CD + (size_t)(i0 + ic) * KK * 2 * D_OUT);
        // Register-cached boundary rows for this i (o-quad = lane*4)
        const float4 c0 = __ldg(bi4 + lane);
        const float4 d0 = __ldg(bi4 + 32 + lane);
        const float4 cL = __ldg(bi4 + 63 * 64 + lane);
        const float4 dL = __ldg(bi4 + 63 * 64 + 32 + lane);

        #pragma unroll 4
        for (int r = 0; r < 16; r++) {
            const int    bl   = wid * 16 + r;
            const int    code = s_idx[ic][bl];    // broadcast
            const float4 w    = s_w[ic][bl];      // broadcast
            if (code < 64) {                       // interior (warp-uniform branch)
                const float4* p = bi4 + code * 64 + lane;
                const float4 y0  = __ldg(p);
                const float4 dd0 = __ldg(p + 32);
                const float4 y1  = __ldg(p + 64);
                const float4 dd1 = __ldg(p + 96);
                acc[r].x += w.x * y0.x + w.y * dd0.x + w.z * y1.x + w.w * dd1.x;
                acc[r].y += w.x * y0.y + w.y * dd0.y + w.z * y1.y + w.w * dd1.y;
                acc[r].z += w.x * y0.z + w.y * dd0.z + w.z * y1.z + w.w * dd1.z;
                acc[r].w += w.x * y0.w + w.y * dd0.w + w.z * y1.w + w.w * dd1.w;
            } else {                               // extrapolation: registers only
                const float4 c = (code == 101) ? c0 : cL;
                const float4 d = (code == 101) ? d0 : dL;
                acc[r].x += c.x + w.y * d.x;
                acc[r].y += c.y + w.y * d.y;
                acc[r].z += c.z + w.y * d.z;
                acc[r].w += c.w + w.y * d.w;
            }
        }
    }

    // Write partials (float4, fully coalesced)
    #pragma unroll
    for (int r = 0; r < 16; r++) {
        const int b = b0 + wid * 16 + r;
        *reinterpret_cast<float4*>(
            g_part + ((size_t)blockIdx.y * B + b) * D_OUT + lane * 4) = acc[r];
    }
}

// ---------------------------------------------------------------------------
// Reduce 8 partial buffers + bias -> out. float4-vectorized.
// ---------------------------------------------------------------------------
__global__ void __launch_bounds__(256) reduce_kernel(const float* __restrict__ bias,
                                                     float* __restrict__ out, int B) {
    const int idx = blockIdx.x * 256 + threadIdx.x;   // float4 index
    const int n4  = B * (D_OUT / 4);
    if (idx >= n4) return;
    const float4* p = reinterpret_cast<const float4*>(g_part);
    const size_t stride = (size_t)B * (D_OUT / 4);
    float4 s = make_float4(0.f, 0.f, 0.f, 0.f);
    #pragma unroll
    for (int c = 0; c < NCHUNK; c++) {
        float4 v = __ldg(p + (size_t)c * stride + idx);
        s.x += v.x; s.y += v.y; s.z += v.z; s.w += v.w;
    }
    const float4 bv = __ldg(reinterpret_cast<const float4*>(bias) + (idx & (D_OUT / 4 - 1)));
    s.x += bv.x; s.y += bv.y; s.z += bv.z; s.w += bv.w;
    reinterpret_cast<float4*>(out)[idx] = s;
}

// ---------------------------------------------------------------------------
extern "C" void kernel_launch(void* const* d_in, const int* in_sizes, int n_in,
                              void* d_out, int out_size) {
    const float* x      = (const float*)d_in[0];   // [B, 128]
    const float* coeffs = (const float*)d_in[1];   // [128, 128, 64]
    const float* bias   = (const float*)d_in[2];   // [128]
    // d_in[3] = knots: uniform linspace(0,1,64) -> baked-in constants.

    const int B = in_sizes[0] / D_IN;              // 4096

    prep_kernel<<<dim3(D_IN, D_OUT / 32), 256>>>(coeffs);
    kan_eval<<<dim3(B / BC, NCHUNK), 256>>>(x, B);
    reduce_kernel<<<(B * (D_OUT / 4) + 255) / 256, 256>>>(bias, (float*)d_out, B);
}